// round 2
// baseline (speedup 1.0000x reference)
#include <cuda_runtime.h>
#include <math.h>

// Problem constants
#define B_ 8
#define C_ 1024
#define N_ 64
#define P_ 32
#define E_ 3
#define H_ 4096
#define O_ 1024
#define T_ (N_ * P_)   // 2048 tokens per batch image
#define A_ (B_ * T_)   // 16384 total tokens

// Scratch (static device globals — allocation-free per harness rules)
__device__ float g_xt[(size_t)A_ * C_];     //  64 MB  [A, C] tokens
__device__ float g_h[(size_t)A_ * H_];      // 256 MB  [A, H] compacted per-expert hidden
__device__ float g_out[(size_t)A_ * O_];    //  64 MB  [A, O] accumulator
__device__ float g_gates[A_ * E_];          // router gates (exactly 0 off top-k)
__device__ int   g_cnt[E_];                 // per-expert compacted token count
__device__ int   g_idx[E_][A_];             // per-expert compacted token indices

__device__ __forceinline__ float gelu_exact(float v) {
    return 0.5f * v * (1.0f + erff(v * 0.70710678118654752440f));
}

// ---------------------------------------------------------------------------
// x [B, C, N, P]  ->  g_xt [A, C]   (per-batch 2D transpose via smem tile)
// ---------------------------------------------------------------------------
__global__ void transpose_in_kernel(const float* __restrict__ x) {
    __shared__ float tile[32][33];
    const int b  = blockIdx.z;
    const int t0 = blockIdx.x * 32;   // token within batch (n*P + p)
    const int c0 = blockIdx.y * 32;   // channel
    const int tx = threadIdx.x, ty = threadIdx.y;
    const float* xb = x + (size_t)b * C_ * T_;
#pragma unroll
    for (int j = 0; j < 4; j++)
        tile[ty + j * 8][tx] = xb[(size_t)(c0 + ty + j * 8) * T_ + t0 + tx];
    __syncthreads();
#pragma unroll
    for (int j = 0; j < 4; j++)
        g_xt[(size_t)(b * T_ + t0 + ty + j * 8) * C_ + c0 + tx] = tile[tx][ty + j * 8];
}

__global__ void zero_cnt_kernel() {
    if (threadIdx.x < E_) g_cnt[threadIdx.x] = 0;
}

// ---------------------------------------------------------------------------
// Noisy top-2-of-3 router + per-expert compaction. One warp per token.
// ---------------------------------------------------------------------------
__global__ void router_kernel(const float* __restrict__ Wg, const float* __restrict__ bg,
                              const float* __restrict__ Wn, const float* __restrict__ bn,
                              const float* __restrict__ noise_u) {
    const int a    = (blockIdx.x * blockDim.x + threadIdx.x) >> 5;
    const int lane = threadIdx.x & 31;
    if (a >= A_) return;
    const float* xr = g_xt + (size_t)a * C_;
    float ag0 = 0.f, ag1 = 0.f, ag2 = 0.f, an0 = 0.f, an1 = 0.f, an2 = 0.f;
    for (int c = lane; c < C_; c += 32) {
        float xv = xr[c];
        ag0 = fmaf(xv, Wg[c * 3 + 0], ag0);
        ag1 = fmaf(xv, Wg[c * 3 + 1], ag1);
        ag2 = fmaf(xv, Wg[c * 3 + 2], ag2);
        an0 = fmaf(xv, Wn[c * 3 + 0], an0);
        an1 = fmaf(xv, Wn[c * 3 + 1], an1);
        an2 = fmaf(xv, Wn[c * 3 + 2], an2);
    }
#pragma unroll
    for (int off = 16; off; off >>= 1) {
        ag0 += __shfl_xor_sync(0xffffffffu, ag0, off);
        ag1 += __shfl_xor_sync(0xffffffffu, ag1, off);
        ag2 += __shfl_xor_sync(0xffffffffu, ag2, off);
        an0 += __shfl_xor_sync(0xffffffffu, an0, off);
        an1 += __shfl_xor_sync(0xffffffffu, an1, off);
        an2 += __shfl_xor_sync(0xffffffffu, an2, off);
    }
    if (lane == 0) {
        float l[3], n[3];
        l[0] = ag0 + bg[0]; l[1] = ag1 + bg[1]; l[2] = ag2 + bg[2];
        n[0] = an0 + bn[0]; n[1] = an1 + bn[1]; n[2] = an2 + bn[2];
        // softmax over noise logits
        float mn = fmaxf(n[0], fmaxf(n[1], n[2]));
        float e0 = expf(n[0] - mn), e1 = expf(n[1] - mn), e2 = expf(n[2] - mn);
        float s = e0 + e1 + e2;
        l[0] += noise_u[a * 3 + 0] * (e0 / s);
        l[1] += noise_u[a * 3 + 1] * (e1 / s);
        l[2] += noise_u[a * 3 + 2] * (e2 / s);
        // top-2 of 3 (stable: earlier index wins ties, matching jax top_k)
        int i1 = 0;
        if (l[1] > l[i1]) i1 = 1;
        if (l[2] > l[i1]) i1 = 2;
        int i2 = -1;
#pragma unroll
        for (int e = 0; e < 3; e++)
            if (e != i1 && (i2 < 0 || l[e] > l[i2])) i2 = e;
        // softmax over {i1, i2}, others exactly 0  (== softmax with -inf mask)
        float m2 = fmaxf(l[i1], l[i2]);
        float x1 = expf(l[i1] - m2), x2 = expf(l[i2] - m2);
        float d = x1 + x2;
        float g[3] = {0.f, 0.f, 0.f};
        g[i1] = x1 / d;
        g[i2] = x2 / d;
        g_gates[a * 3 + 0] = g[0];
        g_gates[a * 3 + 1] = g[1];
        g_gates[a * 3 + 2] = g[2];
        // compaction: push this token onto its two selected experts' lists
        int p1 = atomicAdd(&g_cnt[i1], 1);
        g_idx[i1][p1] = a;
        int p2 = atomicAdd(&g_cnt[i2], 1);
        g_idx[i2][p2] = a;
    }
}

// ---------------------------------------------------------------------------
// g_out[a,o] = sum_e gates[a,e] * b2[e,o]   (bias fold; gates 0 off top-k)
// ---------------------------------------------------------------------------
__global__ void out_init_kernel(const float* __restrict__ b2) {
    const int idx = blockIdx.x * blockDim.x + threadIdx.x;
    const int a = idx >> 10;       // / O_ (1024)
    const int o = idx & 1023;
    g_out[idx] = g_gates[a * 3 + 0] * b2[o]
               + g_gates[a * 3 + 1] * b2[O_ + o]
               + g_gates[a * 3 + 2] * b2[2 * O_ + o];
}

// ---------------------------------------------------------------------------
// Tiled SGEMM over COMPACTED token lists. 128x128x16 block tile, 256 threads,
// 8x8 per-thread tile, global-load/compute overlap.
// MODE 0:  g_h[slot]     = gelu(g_xt[idx[slot]] @ W1e + b1e) * gate   (N=H, K=C)
// MODE 1:  g_out[idx[slot]] += g_h[slot] @ W2e                        (N=O, K=H)
// Blocks with m0 >= cnt[e] exit immediately (fixed worst-case grid for graph).
// ---------------------------------------------------------------------------
template <int MODE>
__global__ void __launch_bounds__(256, 2)
gemm_tile(const float* __restrict__ Bm, const float* __restrict__ bias, int expert) {
    constexpr int Ndim = (MODE == 0) ? H_ : O_;
    constexpr int Kdim = (MODE == 0) ? C_ : H_;

    const int cnt = g_cnt[expert];
    const int m0 = blockIdx.y * 128;
    if (m0 >= cnt) return;
    const int n0 = blockIdx.x * 128;
    const int tid = threadIdx.x;

    __shared__ float As[16][128];   // transposed: As[k][m]
    __shared__ float Bs[16][128];   // Bs[k][n]
    __shared__ int   idx_s[128];

    if (tid < 128) {
        int r = m0 + tid;
        idx_s[tid] = (r < cnt) ? g_idx[expert][r] : 0;
    }
    __syncthreads();

    const int ar = tid >> 2;           // 0..63 (A-tile row; +64 for second)
    const int ac = (tid & 3) << 2;     // 0,4,8,12 (A-tile k-col, float4)
    const int br = tid >> 5;           // 0..7 (B-tile k-row; +8 for second)
    const int bc = (tid & 31) << 2;    // 0..124 (B-tile n-col, float4)
    const int ty = tid >> 4;           // 0..15
    const int tx = tid & 15;           // 0..15

    const float* Ap, * Ap2;
    if (MODE == 0) {
        Ap  = g_xt + (size_t)idx_s[ar] * Kdim;
        Ap2 = g_xt + (size_t)idx_s[ar + 64] * Kdim;
    } else {
        Ap  = g_h + (size_t)(m0 + ar) * Kdim;
        Ap2 = g_h + (size_t)(m0 + ar + 64) * Kdim;
    }
    const float* Bp = Bm + n0;

    float acc[8][8];
#pragma unroll
    for (int i = 0; i < 8; i++)
#pragma unroll
        for (int j = 0; j < 8; j++) acc[i][j] = 0.f;

    // prefetch k-tile 0
    float4 a0 = *(const float4*)(Ap  + ac);
    float4 a1 = *(const float4*)(Ap2 + ac);
    float4 b0 = *(const float4*)(Bp + (size_t)br * Ndim + bc);
    float4 b1 = *(const float4*)(Bp + (size_t)(br + 8) * Ndim + bc);

    for (int k0 = 0; k0 < Kdim; k0 += 16) {
        __syncthreads();
        As[ac + 0][ar] = a0.x; As[ac + 1][ar] = a0.y;
        As[ac + 2][ar] = a0.z; As[ac + 3][ar] = a0.w;
        As[ac + 0][ar + 64] = a1.x; As[ac + 1][ar + 64] = a1.y;
        As[ac + 2][ar + 64] = a1.z; As[ac + 3][ar + 64] = a1.w;
        *(float4*)&Bs[br][bc]     = b0;
        *(float4*)&Bs[br + 8][bc] = b1;
        __syncthreads();
        if (k0 + 16 < Kdim) {   // issue next tile's loads before compute
            a0 = *(const float4*)(Ap  + k0 + 16 + ac);
            a1 = *(const float4*)(Ap2 + k0 + 16 + ac);
            b0 = *(const float4*)(Bp + (size_t)(k0 + 16 + br) * Ndim + bc);
            b1 = *(const float4*)(Bp + (size_t)(k0 + 24 + br) * Ndim + bc);
        }
#pragma unroll
        for (int kk = 0; kk < 16; kk++) {
            float af[8], bf[8];
            *(float4*)(af)     = *(const float4*)&As[kk][ty * 8];
            *(float4*)(af + 4) = *(const float4*)&As[kk][ty * 8 + 4];
            *(float4*)(bf)     = *(const float4*)&Bs[kk][tx * 8];
            *(float4*)(bf + 4) = *(const float4*)&Bs[kk][tx * 8 + 4];
#pragma unroll
            for (int i = 0; i < 8; i++)
#pragma unroll
                for (int j = 0; j < 8; j++)
                    acc[i][j] = fmaf(af[i], bf[j], acc[i][j]);
        }
    }

    if (MODE == 0) {
        // store to compacted g_h rows (pad rows written too; never consumed)
#pragma unroll
        for (int i = 0; i < 8; i++) {
            const int slot = ty * 8 + i;                 // row within tile
            const int tok  = idx_s[slot];
            const float gate = g_gates[tok * E_ + expert];
            float* crow = g_h + (size_t)(m0 + slot) * Ndim + n0 + tx * 8;
            float v[8];
#pragma unroll
            for (int j = 0; j < 8; j++) {
                float t = acc[i][j] + bias[n0 + tx * 8 + j];
                v[j] = gelu_exact(t) * gate;
            }
            *(float4*)(crow)     = make_float4(v[0], v[1], v[2], v[3]);
            *(float4*)(crow + 4) = make_float4(v[4], v[5], v[6], v[7]);
        }
    } else {
        // scatter-accumulate into g_out[token]; mask pad rows.
        // Safe: expert kernels serialize on the stream; within one expert each
        // token appears exactly once in the list.
#pragma unroll
        for (int i = 0; i < 8; i++) {
            const int slot = ty * 8 + i;
            if (m0 + slot >= cnt) continue;
            const int tok = idx_s[slot];
            float* crow = g_out + (size_t)tok * Ndim + n0 + tx * 8;
            float4 c0 = *(const float4*)(crow);
            float4 c1 = *(const float4*)(crow + 4);
            c0.x += acc[i][0]; c0.y += acc[i][1]; c0.z += acc[i][2]; c0.w += acc[i][3];
            c1.x += acc[i][4]; c1.y += acc[i][5]; c1.z += acc[i][6]; c1.w += acc[i][7];
            *(float4*)(crow)     = c0;
            *(float4*)(crow + 4) = c1;
        }
    }
}

// ---------------------------------------------------------------------------
// g_out [A, O]  ->  d_out [B, O, N, P]
// ---------------------------------------------------------------------------
__global__ void transpose_out_kernel(float* __restrict__ out) {
    __shared__ float tile[32][33];
    const int b  = blockIdx.z;
    const int o0 = blockIdx.x * 32;
    const int t0 = blockIdx.y * 32;
    const int tx = threadIdx.x, ty = threadIdx.y;
#pragma unroll
    for (int j = 0; j < 4; j++)
        tile[ty + j * 8][tx] = g_out[(size_t)(b * T_ + t0 + ty + j * 8) * O_ + o0 + tx];
    __syncthreads();
#pragma unroll
    for (int j = 0; j < 4; j++)
        out[(size_t)(b * O_ + o0 + ty + j * 8) * T_ + t0 + tx] = tile[tx][ty + j * 8];
}

// ---------------------------------------------------------------------------
extern "C" void kernel_launch(void* const* d_in, const int* in_sizes, int n_in,
                              void* d_out, int out_size) {
    (void)in_sizes; (void)n_in; (void)out_size;
    const float* x  = (const float*)d_in[0];
    const float* Wg = (const float*)d_in[1];
    const float* bg = (const float*)d_in[2];
    const float* Wn = (const float*)d_in[3];
    const float* bn = (const float*)d_in[4];
    const float* W1 = (const float*)d_in[5];
    const float* b1 = (const float*)d_in[6];
    const float* W2 = (const float*)d_in[7];
    const float* b2 = (const float*)d_in[8];
    const float* nu = (const float*)d_in[9];
    float* out = (float*)d_out;

    transpose_in_kernel<<<dim3(T_ / 32, C_ / 32, B_), dim3(32, 8)>>>(x);
    zero_cnt_kernel<<<1, 32>>>();
    router_kernel<<<A_ / 8, 256>>>(Wg, bg, Wn, bn, nu);
    out_init_kernel<<<(A_ * O_) / 256, 256>>>(b2);
    for (int e = 0; e < E_; e++) {
        gemm_tile<0><<<dim3(H_ / 128, A_ / 128), 256>>>(
            W1 + (size_t)e * C_ * H_, b1 + (size_t)e * H_, e);
        gemm_tile<1><<<dim3(O_ / 128, A_ / 128), 256>>>(
            W2 + (size_t)e * H_ * O_, nullptr, e);
    }
    transpose_out_kernel<<<dim3(O_ / 32, T_ / 32, B_), dim3(32, 8)>>>(out);
}

// round 8
// speedup vs baseline: 1.8366x; 1.8366x over previous
#include <cuda_runtime.h>
#include <cuda_bf16.h>
#include <math.h>
#include <stdint.h>

// Problem constants
#define B_ 8
#define C_ 1024
#define N_ 64
#define P_ 32
#define E_ 3
#define H_ 4096
#define O_ 1024
#define T_ (N_ * P_)   // 2048 tokens per batch image
#define A_ (B_ * T_)   // 16384 total tokens

// ---------------------------------------------------------------------------
// Device scratch (static globals — allocation-free per harness rules)
// ---------------------------------------------------------------------------
__device__ float    g_xt[(size_t)A_ * C_];          //  64 MB fp32 tokens (router)
__device__ uint32_t g_xpk[(size_t)A_ * C_];         //  64 MB packed (bf16 hi|lo)
__device__ uint32_t g_w1t[(size_t)E_ * H_ * C_];    //  50 MB W1^T packed [E][H][C]
__device__ uint32_t g_w2t[(size_t)E_ * O_ * H_];    //  50 MB W2^T packed [E][O][H]
__device__ uint32_t g_hpk[(size_t)A_ * H_];         // 256 MB hidden packed (compacted slots)
__device__ float    g_out[(size_t)A_ * O_];         //  64 MB fp32 accumulator
__device__ float    g_gates[A_ * E_];
__device__ int      g_cnt[E_];
__device__ int      g_idx[E_][A_];

__device__ __forceinline__ float gelu_exact(float v) {
    return 0.5f * v * (1.0f + erff(v * 0.70710678118654752440f));
}

__device__ __forceinline__ uint32_t pack_hl(float v) {
    __nv_bfloat16 h = __float2bfloat16(v);
    float hf = __bfloat162float(h);
    __nv_bfloat16 l = __float2bfloat16(v - hf);
    return (uint32_t)__bfloat16_as_ushort(h) | ((uint32_t)__bfloat16_as_ushort(l) << 16);
}

// mma.sync m16n8k16 row.col f32.bf16.bf16.f32 (sm_80 baseline — OK on compute_103)
#define MMA_BF16(d, a, b0v, b1v) \
    asm volatile("mma.sync.aligned.m16n8k16.row.col.f32.bf16.bf16.f32 " \
        "{%0,%1,%2,%3}, {%4,%5,%6,%7}, {%8,%9}, {%0,%1,%2,%3};" \
        : "+f"((d)[0]), "+f"((d)[1]), "+f"((d)[2]), "+f"((d)[3]) \
        : "r"((a)[0]), "r"((a)[1]), "r"((a)[2]), "r"((a)[3]), "r"(b0v), "r"(b1v))

// ---------------------------------------------------------------------------
// x [B, C, N, P] -> g_xt fp32 [A, C]  +  g_xpk packed [A, C]
// ---------------------------------------------------------------------------
__global__ void transpose_in_kernel(const float* __restrict__ x) {
    __shared__ float tile[32][33];
    const int b  = blockIdx.z;
    const int t0 = blockIdx.x * 32;
    const int c0 = blockIdx.y * 32;
    const int tx = threadIdx.x, ty = threadIdx.y;
    const float* xb = x + (size_t)b * C_ * T_;
#pragma unroll
    for (int j = 0; j < 4; j++)
        tile[ty + j * 8][tx] = xb[(size_t)(c0 + ty + j * 8) * T_ + t0 + tx];
    __syncthreads();
#pragma unroll
    for (int j = 0; j < 4; j++) {
        float v = tile[tx][ty + j * 8];
        size_t o = (size_t)(b * T_ + t0 + ty + j * 8) * C_ + c0 + tx;
        g_xt[o]  = v;
        g_xpk[o] = pack_hl(v);
    }
}

// ---------------------------------------------------------------------------
// W [E][R][S] row-major -> Wt packed [E][S][R]
// ---------------------------------------------------------------------------
__global__ void wtrans_kernel(const float* __restrict__ W, uint32_t* __restrict__ Wt,
                              int R, int S) {
    __shared__ float tile[32][33];
    const int e  = blockIdx.z;
    const int s0 = blockIdx.x * 32;
    const int r0 = blockIdx.y * 32;
    const int tx = threadIdx.x, ty = threadIdx.y;
    const float* We = W + (size_t)e * R * S;
    uint32_t* Wte   = Wt + (size_t)e * R * S;
#pragma unroll
    for (int j = 0; j < 4; j++)
        tile[ty + j * 8][tx] = We[(size_t)(r0 + ty + j * 8) * S + s0 + tx];
    __syncthreads();
#pragma unroll
    for (int j = 0; j < 4; j++)
        Wte[(size_t)(s0 + ty + j * 8) * R + r0 + tx] = pack_hl(tile[tx][ty + j * 8]);
}

__global__ void zero_cnt_kernel() {
    if (threadIdx.x < E_) g_cnt[threadIdx.x] = 0;
}

// ---------------------------------------------------------------------------
// Noisy top-2-of-3 router + compaction. One warp per token.
// ---------------------------------------------------------------------------
__global__ void router_kernel(const float* __restrict__ Wg, const float* __restrict__ bg,
                              const float* __restrict__ Wn, const float* __restrict__ bn,
                              const float* __restrict__ noise_u) {
    const int a    = (blockIdx.x * blockDim.x + threadIdx.x) >> 5;
    const int lane = threadIdx.x & 31;
    if (a >= A_) return;
    const float* xr = g_xt + (size_t)a * C_;
    float ag0 = 0.f, ag1 = 0.f, ag2 = 0.f, an0 = 0.f, an1 = 0.f, an2 = 0.f;
    for (int c = lane; c < C_; c += 32) {
        float xv = xr[c];
        ag0 = fmaf(xv, Wg[c * 3 + 0], ag0);
        ag1 = fmaf(xv, Wg[c * 3 + 1], ag1);
        ag2 = fmaf(xv, Wg[c * 3 + 2], ag2);
        an0 = fmaf(xv, Wn[c * 3 + 0], an0);
        an1 = fmaf(xv, Wn[c * 3 + 1], an1);
        an2 = fmaf(xv, Wn[c * 3 + 2], an2);
    }
#pragma unroll
    for (int off = 16; off; off >>= 1) {
        ag0 += __shfl_xor_sync(0xffffffffu, ag0, off);
        ag1 += __shfl_xor_sync(0xffffffffu, ag1, off);
        ag2 += __shfl_xor_sync(0xffffffffu, ag2, off);
        an0 += __shfl_xor_sync(0xffffffffu, an0, off);
        an1 += __shfl_xor_sync(0xffffffffu, an1, off);
        an2 += __shfl_xor_sync(0xffffffffu, an2, off);
    }
    if (lane == 0) {
        float l[3], n[3];
        l[0] = ag0 + bg[0]; l[1] = ag1 + bg[1]; l[2] = ag2 + bg[2];
        n[0] = an0 + bn[0]; n[1] = an1 + bn[1]; n[2] = an2 + bn[2];
        float mn = fmaxf(n[0], fmaxf(n[1], n[2]));
        float e0 = expf(n[0] - mn), e1 = expf(n[1] - mn), e2 = expf(n[2] - mn);
        float s = e0 + e1 + e2;
        l[0] += noise_u[a * 3 + 0] * (e0 / s);
        l[1] += noise_u[a * 3 + 1] * (e1 / s);
        l[2] += noise_u[a * 3 + 2] * (e2 / s);
        int i1 = 0;
        if (l[1] > l[i1]) i1 = 1;
        if (l[2] > l[i1]) i1 = 2;
        int i2 = -1;
#pragma unroll
        for (int e = 0; e < 3; e++)
            if (e != i1 && (i2 < 0 || l[e] > l[i2])) i2 = e;
        float m2 = fmaxf(l[i1], l[i2]);
        float x1 = expf(l[i1] - m2), x2 = expf(l[i2] - m2);
        float d = x1 + x2;
        float g[3] = {0.f, 0.f, 0.f};
        g[i1] = x1 / d;
        g[i2] = x2 / d;
        g_gates[a * 3 + 0] = g[0];
        g_gates[a * 3 + 1] = g[1];
        g_gates[a * 3 + 2] = g[2];
        int p1 = atomicAdd(&g_cnt[i1], 1);
        g_idx[i1][p1] = a;
        int p2 = atomicAdd(&g_cnt[i2], 1);
        g_idx[i2][p2] = a;
    }
}

// g_out[a,o] = sum_e gates[a,e] * b2[e,o]
__global__ void out_init_kernel(const float* __restrict__ b2) {
    const int idx = blockIdx.x * blockDim.x + threadIdx.x;
    const int a = idx >> 10;
    const int o = idx & 1023;
    g_out[idx] = g_gates[a * 3 + 0] * b2[o]
               + g_gates[a * 3 + 1] * b2[O_ + o]
               + g_gates[a * 3 + 2] * b2[2 * O_ + o];
}

// ---------------------------------------------------------------------------
// Split-bf16 GEMM on mma.sync (m16n8k16).  Block tile 128x128, 8 warps (2x4),
// warp tile 64x32, K-chunk 32 double-buffered in dynamic smem.
// D(fp32) = Ahi@Bhi^T + Ahi@Blo^T + Alo@Bhi^T over packed u32 (bf16 hi|lo).
// MODE 0: A = gathered x rows, B = W1^T; epilogue gelu(.+b1)*gate -> g_hpk
// MODE 1: A = g_hpk slots,     B = W2^T; epilogue += into g_out[token]
// ---------------------------------------------------------------------------
#define SA 36                         // smem row stride (u32) — pad vs conflicts
#define TILE_U32 (128 * SA)           // 4608 u32 per operand tile
#define BUF_U32  (2 * TILE_U32)       // A + B per buffer
#define SMEM_GEMM_BYTES (2 * BUF_U32 * 4)   // 73728 B

template <int MODE>
__global__ void __launch_bounds__(256)
gemm_mma(const uint32_t* __restrict__ wpk, const float* __restrict__ bias, int expert) {
    constexpr int Kdim   = (MODE == 0) ? C_ : H_;
    constexpr int NCHUNK = Kdim / 32;

    const int cnt = g_cnt[expert];
    const int m0  = blockIdx.y * 128;
    if (m0 >= cnt) return;
    const int n0  = blockIdx.x * 128;
    const int tid  = threadIdx.x;
    const int lane = tid & 31;
    const int wid  = tid >> 5;
    const int wm   = wid >> 2;        // 0..1  (64-row halves)
    const int wn   = wid & 3;         // 0..3  (32-col quarters)

    extern __shared__ uint32_t sm[];
    __shared__ int idx_s[128];
    if (tid < 128) {
        int r = m0 + tid;
        idx_s[tid] = (r < cnt) ? g_idx[expert][r] : 0;
    }
    __syncthreads();

    const int grow = tid >> 3;        // 0..31
    const int gcol = (tid & 7) * 4;   // u32 col of uint4

    uint4 ra[4], rb[4];
    auto gload = [&](int c) {
        const int k0 = c * 32;
#pragma unroll
        for (int i = 0; i < 4; i++) {
            int row = grow + 32 * i;
            const uint32_t* srcA = (MODE == 0)
                ? g_xpk + (size_t)idx_s[row] * C_ + k0 + gcol
                : g_hpk + (size_t)(m0 + row) * H_ + k0 + gcol;
            ra[i] = *(const uint4*)srcA;
            rb[i] = *(const uint4*)(wpk + (size_t)(n0 + row) * Kdim + k0 + gcol);
        }
    };
    auto sstore = [&](int b) {
        uint32_t* A  = sm + b * BUF_U32;
        uint32_t* Bm = A + TILE_U32;
#pragma unroll
        for (int i = 0; i < 4; i++) {
            int row = grow + 32 * i;
            *(uint4*)(A  + row * SA + gcol) = ra[i];
            *(uint4*)(Bm + row * SA + gcol) = rb[i];
        }
    };

    float acc[4][4][4];
#pragma unroll
    for (int mi = 0; mi < 4; mi++)
#pragma unroll
        for (int ni = 0; ni < 4; ni++)
#pragma unroll
            for (int k = 0; k < 4; k++) acc[mi][ni][k] = 0.f;

    gload(0);
    sstore(0);
    __syncthreads();

    for (int c = 0; c < NCHUNK; c++) {
        if (c + 1 < NCHUNK) gload(c + 1);
        const uint32_t* A  = sm + (c & 1) * BUF_U32;
        const uint32_t* Bm = A + TILE_U32;
#pragma unroll
        for (int kk = 0; kk < 32; kk += 16) {
            const int kc = kk + (lane & 3) * 2;
            uint32_t bhi[4][2], blo[4][2];
#pragma unroll
            for (int ni = 0; ni < 4; ni++) {
                int n = wn * 32 + ni * 8 + (lane >> 2);
                uint2 p0 = *(const uint2*)(Bm + n * SA + kc);
                uint2 p1 = *(const uint2*)(Bm + n * SA + kc + 8);
                bhi[ni][0] = __byte_perm(p0.x, p0.y, 0x5410);
                blo[ni][0] = __byte_perm(p0.x, p0.y, 0x7632);
                bhi[ni][1] = __byte_perm(p1.x, p1.y, 0x5410);
                blo[ni][1] = __byte_perm(p1.x, p1.y, 0x7632);
            }
#pragma unroll
            for (int mi = 0; mi < 4; mi++) {
                int r = wm * 64 + mi * 16 + (lane >> 2);
                uint2 q0 = *(const uint2*)(A + r * SA + kc);
                uint2 q1 = *(const uint2*)(A + (r + 8) * SA + kc);
                uint2 q2 = *(const uint2*)(A + r * SA + kc + 8);
                uint2 q3 = *(const uint2*)(A + (r + 8) * SA + kc + 8);
                uint32_t ahi[4], alo[4];
                ahi[0] = __byte_perm(q0.x, q0.y, 0x5410);
                alo[0] = __byte_perm(q0.x, q0.y, 0x7632);
                ahi[1] = __byte_perm(q1.x, q1.y, 0x5410);
                alo[1] = __byte_perm(q1.x, q1.y, 0x7632);
                ahi[2] = __byte_perm(q2.x, q2.y, 0x5410);
                alo[2] = __byte_perm(q2.x, q2.y, 0x7632);
                ahi[3] = __byte_perm(q3.x, q3.y, 0x5410);
                alo[3] = __byte_perm(q3.x, q3.y, 0x7632);
#pragma unroll
                for (int ni = 0; ni < 4; ni++) {
                    MMA_BF16(acc[mi][ni], ahi, bhi[ni][0], bhi[ni][1]);
                    MMA_BF16(acc[mi][ni], ahi, blo[ni][0], blo[ni][1]);
                    MMA_BF16(acc[mi][ni], alo, bhi[ni][0], bhi[ni][1]);
                }
            }
        }
        __syncthreads();
        if (c + 1 < NCHUNK) {
            sstore((c + 1) & 1);
            __syncthreads();
        }
    }

    // ---- epilogue ----------------------------------------------------------
    if (MODE == 0) {
#pragma unroll
        for (int mi = 0; mi < 4; mi++) {
            int ma = wm * 64 + mi * 16 + (lane >> 2);
            int mb = ma + 8;
            float ga = g_gates[idx_s[ma] * E_ + expert];
            float gb = g_gates[idx_s[mb] * E_ + expert];
#pragma unroll
            for (int ni = 0; ni < 4; ni++) {
                int n = wn * 32 + ni * 8 + (lane & 3) * 2;
                float bv0 = bias[n0 + n], bv1 = bias[n0 + n + 1];
                uint2 va, vb;
                va.x = pack_hl(gelu_exact(acc[mi][ni][0] + bv0) * ga);
                va.y = pack_hl(gelu_exact(acc[mi][ni][1] + bv1) * ga);
                vb.x = pack_hl(gelu_exact(acc[mi][ni][2] + bv0) * gb);
                vb.y = pack_hl(gelu_exact(acc[mi][ni][3] + bv1) * gb);
                *(uint2*)&g_hpk[(size_t)(m0 + ma) * H_ + n0 + n] = va;
                *(uint2*)&g_hpk[(size_t)(m0 + mb) * H_ + n0 + n] = vb;
            }
        }
    } else {
#pragma unroll
        for (int mi = 0; mi < 4; mi++) {
            int ma = wm * 64 + mi * 16 + (lane >> 2);
            int mb = ma + 8;
            int toka = idx_s[ma], tokb = idx_s[mb];
            bool oka = (m0 + ma) < cnt, okb = (m0 + mb) < cnt;
#pragma unroll
            for (int ni = 0; ni < 4; ni++) {
                int n = wn * 32 + ni * 8 + (lane & 3) * 2;
                if (oka) {
                    float2* p = (float2*)&g_out[(size_t)toka * O_ + n0 + n];
                    float2 v = *p;
                    v.x += acc[mi][ni][0]; v.y += acc[mi][ni][1];
                    *p = v;
                }
                if (okb) {
                    float2* p = (float2*)&g_out[(size_t)tokb * O_ + n0 + n];
                    float2 v = *p;
                    v.x += acc[mi][ni][2]; v.y += acc[mi][ni][3];
                    *p = v;
                }
            }
        }
    }
}

// ---------------------------------------------------------------------------
// g_out [A, O] -> d_out [B, O, N, P]
// ---------------------------------------------------------------------------
__global__ void transpose_out_kernel(float* __restrict__ out) {
    __shared__ float tile[32][33];
    const int b  = blockIdx.z;
    const int o0 = blockIdx.x * 32;
    const int t0 = blockIdx.y * 32;
    const int tx = threadIdx.x, ty = threadIdx.y;
#pragma unroll
    for (int j = 0; j < 4; j++)
        tile[ty + j * 8][tx] = g_out[(size_t)(b * T_ + t0 + ty + j * 8) * O_ + o0 + tx];
    __syncthreads();
#pragma unroll
    for (int j = 0; j < 4; j++)
        out[(size_t)(b * O_ + o0 + ty + j * 8) * T_ + t0 + tx] = tile[tx][ty + j * 8];
}

// ---------------------------------------------------------------------------
extern "C" void kernel_launch(void* const* d_in, const int* in_sizes, int n_in,
                              void* d_out, int out_size) {
    (void)in_sizes; (void)n_in; (void)out_size;
    const float* x  = (const float*)d_in[0];
    const float* Wg = (const float*)d_in[1];
    const float* bg = (const float*)d_in[2];
    const float* Wn = (const float*)d_in[3];
    const float* bn = (const float*)d_in[4];
    const float* W1 = (const float*)d_in[5];
    const float* b1 = (const float*)d_in[6];
    const float* W2 = (const float*)d_in[7];
    const float* b2 = (const float*)d_in[8];
    const float* nu = (const float*)d_in[9];
    float* out = (float*)d_out;

    // idempotent, not a stream op (graph-capture safe)
    cudaFuncSetAttribute(gemm_mma<0>, cudaFuncAttributeMaxDynamicSharedMemorySize, SMEM_GEMM_BYTES);
    cudaFuncSetAttribute(gemm_mma<1>, cudaFuncAttributeMaxDynamicSharedMemorySize, SMEM_GEMM_BYTES);

    uint32_t* w1t; cudaGetSymbolAddress((void**)&w1t, g_w1t);
    uint32_t* w2t; cudaGetSymbolAddress((void**)&w2t, g_w2t);

    transpose_in_kernel<<<dim3(T_ / 32, C_ / 32, B_), dim3(32, 8)>>>(x);
    zero_cnt_kernel<<<1, 32>>>();
    router_kernel<<<A_ / 8, 256>>>(Wg, bg, Wn, bn, nu);
    out_init_kernel<<<(A_ * O_) / 256, 256>>>(b2);
    wtrans_kernel<<<dim3(H_ / 32, C_ / 32, E_), dim3(32, 8)>>>(W1, w1t, C_, H_);
    wtrans_kernel<<<dim3(O_ / 32, H_ / 32, E_), dim3(32, 8)>>>(W2, w2t, H_, O_);
    for (int e = 0; e < E_; e++) {
        gemm_mma<0><<<dim3(H_ / 128, A_ / 128), 256, SMEM_GEMM_BYTES>>>(
            w1t + (size_t)e * H_ * C_, b1 + (size_t)e * H_, e);
        gemm_mma<1><<<dim3(O_ / 128, A_ / 128), 256, SMEM_GEMM_BYTES>>>(
            w2t + (size_t)e * O_ * H_, nullptr, e);
    }
    transpose_out_kernel<<<dim3(O_ / 32, T_ / 32, B_), dim3(32, 8)>>>(out);
}